// round 11
// baseline (speedup 1.0000x reference)
#include <cuda_runtime.h>
#include <mma.h>
#include <math.h>
#include <cstdint>

using namespace nvcuda;

#define FD    1024
#define SEM   300
#define NWAY  5
#define BS    32
#define NB    512
#define NQ    75
#define BTOT  (BS*NWAY)     // 160
#define CATD  (FD+SEM)      // 1324

#define MNq   (BTOT*FD)     // 163840
#define MNk   (BTOT*CATD)   // 211840
#define SLABK (BTOT*1408)
#define SLABG (BS*1408)
#define SLABF (BS*FD)

#define SMEMF 12800
#define BUFF  6400

// ---------------- scratch ----------------
__device__ __align__(32) float g_scal[BTOT*SEM];
__device__ __align__(32) float g_gv  [BS*FD];
__device__ __align__(32) float g_gs  [BS*SEM];
__device__ __align__(32) float g_q   [BTOT*FD];
__device__ __align__(32) float g_qkg [BTOT*FD];    // UNGATED qk (visual part)
__device__ __align__(32) float g_qksg[BTOT*SEM];   // UNGATED qk (semantic part)
__device__ __align__(32) float g_scr [BTOT*NB];
__device__ __align__(32) float g_avgp[4*BS*CATD];
__device__ __align__(32) float g_mixp[8*SLABF];
__device__ __align__(32) float g_part [16*MNq];
__device__ __align__(32) float g_part2[14*SLABG];
__device__ unsigned int g_barrier;

// ---------------- software grid barrier ----------------
__device__ __forceinline__ void gsync(int &gen)
{
    __syncthreads();
    if (threadIdx.x == 0) {
        __threadfence();
        atomicAdd(&g_barrier, 1u);
        unsigned target = (unsigned)gridDim.x * (unsigned)gen;
        unsigned v;
        do {
            asm volatile("ld.acquire.gpu.u32 %0, [%1];" : "=r"(v) : "l"(&g_barrier) : "memory");
            if (v >= target) break;
            __nanosleep(32);
        } while (true);
    }
    __syncthreads();
    gen++;
}

__device__ __forceinline__ float d4(float4 a, float4 b)
{ return a.x*b.x + a.y*b.y + a.z*b.z + a.w*b.w; }

__device__ __forceinline__ uint64_t mkpolicy()
{
    uint64_t p;
    asm volatile("createpolicy.fractional.L2::evict_last.b64 %0, 1.0;" : "=l"(p));
    return p;
}

__device__ __forceinline__ float4 ldg_el(const float4* p, uint64_t pol)
{
    float4 v;
    asm volatile("ld.global.L2::cache_hint.v4.f32 {%0,%1,%2,%3}, [%4], %5;"
        : "=f"(v.x), "=f"(v.y), "=f"(v.z), "=f"(v.w) : "l"(p), "l"(pol));
    return v;
}

__device__ __forceinline__ void cp16(uint32_t saddr, const void* g, bool pred)
{
    asm volatile("cp.async.ca.shared.global [%0], [%1], 16, %2;"
        :: "r"(saddr), "l"(g), "r"(pred ? 16 : 0));
}

typedef wmma::fragment<wmma::matrix_a, 16,16,8, wmma::precision::tf32, wmma::row_major> FragA;
typedef wmma::fragment<wmma::matrix_b, 16,16,8, wmma::precision::tf32, wmma::row_major> FragBR;
typedef wmma::fragment<wmma::matrix_b, 16,16,8, wmma::precision::tf32, wmma::col_major> FragBC;
typedef wmma::fragment<wmma::accumulator, 16,16,8, float> FragC;

template<class F>
__device__ __forceinline__ void split_frag(F& hi, F& lo)
{
#pragma unroll
    for (int i = 0; i < hi.num_elements; i++) {
        float r = hi.x[i];
        float h = wmma::__float_to_tf32(r);
        hi.x[i] = h;
        lo.x[i] = wmma::__float_to_tf32(r - h);
    }
}

template<bool BTR>
__device__ __forceinline__ void mma_tile(float* As, float* Bs, int mrow, int nq,
                                         FragC& c0, FragC& c1)
{
#pragma unroll
    for (int kk = 0; kk < 32; kk += 8) {
        FragA ah, al;
        wmma::load_matrix_sync(ah, As + mrow*16*40 + kk, 40);
        split_frag(ah, al);
        if (!BTR) {
            FragBR b0h,b0l,b1h,b1l;
            wmma::load_matrix_sync(b0h, Bs + kk*136 + nq*32, 136);
            wmma::load_matrix_sync(b1h, Bs + kk*136 + nq*32 + 16, 136);
            split_frag(b0h, b0l); split_frag(b1h, b1l);
            wmma::mma_sync(c0, ah, b0h, c0);
            wmma::mma_sync(c0, ah, b0l, c0);
            wmma::mma_sync(c0, al, b0h, c0);
            wmma::mma_sync(c1, ah, b1h, c1);
            wmma::mma_sync(c1, ah, b1l, c1);
            wmma::mma_sync(c1, al, b1h, c1);
        } else {
            FragBC b0h,b0l,b1h,b1l;
            wmma::load_matrix_sync(b0h, Bs + (nq*32)*40 + kk, 40);
            wmma::load_matrix_sync(b1h, Bs + (nq*32+16)*40 + kk, 40);
            split_frag(b0h, b0l); split_frag(b1h, b1l);
            wmma::mma_sync(c0, ah, b0h, c0);
            wmma::mma_sync(c0, ah, b0l, c0);
            wmma::mma_sync(c0, al, b0h, c0);
            wmma::mma_sync(c1, ah, b1h, c1);
            wmma::mma_sync(c1, ah, b1l, c1);
            wmma::mma_sync(c1, al, b1h, c1);
        }
    }
}

template<bool BTR>
__device__ __forceinline__ void gemm_pipe(
    const float* __restrict__ A, int M, int K, int lda,
    const float* __restrict__ B1, const float* __restrict__ B2,
    int N1, int N, int ldb1, int ldb2,
    float* __restrict__ part, size_t slab, int ldp,
    int m0, int n0, int kt0, int kt1, float* __restrict__ smbase)
{
    const int t = threadIdx.x;
    const int warp = t >> 5, mrow = warp >> 2, nq = warp & 3;
    FragC c0, c1;
    wmma::fill_fragment(c0, 0.f);
    wmma::fill_fragment(c1, 0.f);

    auto issue = [&](int kt, int bufi) {
        float* As = smbase + bufi*BUFF;
        float* Bs = As + 1280;
        int k0 = kt*32;
        {
            int mm = t >> 3, kq = t & 7;
            int mg = m0 + mm, kg = k0 + kq*4;
            bool ok = (mg < M) && (kg < K);
            uint32_t sa = (uint32_t)__cvta_generic_to_shared(&As[mm*40 + kq*4]);
            cp16(sa, &A[(size_t)mg*lda + kg], ok);
        }
        if (!BTR) {
            int kk = t >> 3, cc = t & 7;
            int kg = k0 + kk;
#pragma unroll
            for (int j = 0; j < 4; j++) {
                int nn = (cc + 8*j)*4;
                int ng = n0 + nn;
                bool ok = (kg < K) && (ng < N);
                const float* g = (ng < N1) ? &B1[(size_t)kg*ldb1 + ng]
                                           : &B2[(size_t)kg*ldb2 + (ng - N1)];
                uint32_t sa = (uint32_t)__cvta_generic_to_shared(&Bs[kk*136 + nn]);
                cp16(sa, g, ok);
            }
        } else {
            int n = t >> 1, half = t & 1;
            int ng = n0 + n;
            bool okrow = ng < N;
            const float* brow = okrow ? ((ng < N1) ? &B1[(size_t)ng*ldb1]
                                                   : &B2[(size_t)(ng-N1)*ldb2]) : B1;
#pragma unroll
            for (int j = 0; j < 4; j++) {
                int kg = k0 + half*16 + j*4;
                bool ok = okrow && (kg < K);
                uint32_t sa = (uint32_t)__cvta_generic_to_shared(&Bs[n*40 + half*16 + j*4]);
                cp16(sa, &brow[kg], ok);
            }
        }
        asm volatile("cp.async.commit_group;");
    };

    issue(kt0, 0);
    for (int kt = kt0; kt < kt1; kt++) {
        int bufi = (kt - kt0) & 1;
        bool more = (kt + 1 < kt1);
        if (more) issue(kt + 1, bufi ^ 1);
        if (more) asm volatile("cp.async.wait_group 1;");
        else      asm volatile("cp.async.wait_group 0;");
        __syncthreads();
        float* As = smbase + bufi*BUFF;
        mma_tile<BTR>(As, As + 1280, mrow, nq, c0, c1);
        __syncthreads();
    }
    float* cb = part + slab + (size_t)(m0 + mrow*16)*ldp + n0 + nq*32;
    wmma::store_matrix_sync(cb,      c0, ldp, wmma::mem_row_major);
    wmma::store_matrix_sync(cb + 16, c1, ldp, wmma::mem_row_major);
}

template<bool REDA, bool GATEA>
__device__ __forceinline__ void gemm_w(
    const float* __restrict__ A, int M, int K, int lda,
    int Zred, size_t slabA, float ascale, const float* __restrict__ gateA,
    const float* __restrict__ B1, const float* __restrict__ B2,
    int N1, int N, int ldb1, int ldb2,
    float* __restrict__ part, size_t slab, int ldp,
    int m0, int n0, int kt0, int kt1, float* __restrict__ smbase)
{
    const int t = threadIdx.x;
    const int warp = t >> 5, mrow = warp >> 2, nq = warp & 3;
    float* As = smbase;
    float* Bs = smbase + 1280;
    FragC c0, c1;
    wmma::fill_fragment(c0, 0.f);
    wmma::fill_fragment(c1, 0.f);

    for (int kt = kt0; kt < kt1; kt++) {
        int k0 = kt*32;
        {
            int mm = t >> 3, kq = (t & 7)*4;
            int mg = m0 + mm, kg = k0 + kq;
            float4 v = make_float4(0,0,0,0);
            if (mg < M && kg + 3 < K) {
                if (REDA) {
                    for (int z = 0; z < Zred; z++) {
                        float4 w = *(const float4*)&A[(size_t)z*slabA + (size_t)mg*lda + kg];
                        v.x+=w.x; v.y+=w.y; v.z+=w.z; v.w+=w.w;
                    }
                } else v = *(const float4*)&A[(size_t)mg*lda + kg];
                v.x*=ascale; v.y*=ascale; v.z*=ascale; v.w*=ascale;
                if (GATEA) {
                    float4 g = *(const float4*)&gateA[(size_t)mg*lda + kg];
                    v.x*=g.x; v.y*=g.y; v.z*=g.z; v.w*=g.w;
                }
            } else if (mg < M) {
                float tmp[4] = {0,0,0,0};
                for (int j = 0; j < 4; j++) {
                    int k2 = kg + j;
                    if (k2 < K) {
                        float s = 0.f;
                        if (REDA) { for (int z=0; z<Zred; z++) s += A[(size_t)z*slabA + (size_t)mg*lda + k2]; }
                        else s = A[(size_t)mg*lda + k2];
                        s *= ascale;
                        if (GATEA) s *= gateA[(size_t)mg*lda + k2];
                        tmp[j] = s;
                    }
                }
                v = make_float4(tmp[0],tmp[1],tmp[2],tmp[3]);
            }
            *(float4*)&As[ (t>>3)*40 + (t&7)*4 ] = v;
        }
        {
            int kk = t >> 3, cc = t & 7;
            int kg = k0 + kk;
#pragma unroll
            for (int j = 0; j < 4; j++) {
                int nn = (cc + 8*j)*4;
                int ng = n0 + nn;
                float4 v = make_float4(0,0,0,0);
                if (kg < K && ng < N) {
                    if (ng < N1) v = *(const float4*)&B1[(size_t)kg*ldb1 + ng];
                    else         v = *(const float4*)&B2[(size_t)kg*ldb2 + (ng-N1)];
                }
                *(float4*)&Bs[kk*136 + nn] = v;
            }
        }
        __syncthreads();
        mma_tile<false>(As, Bs, mrow, nq, c0, c1);
        __syncthreads();
    }
    float* cb = part + slab + (size_t)(m0 + mrow*16)*ldp + n0 + nq*32;
    wmma::store_matrix_sync(cb,      c0, ldp, wmma::mem_row_major);
    wmma::store_matrix_sync(cb + 16, c1, ldp, wmma::mem_row_major);
}

// stage unit counts (q-chain first, bank passes packed at the end)
#define U_MLP   40
#define U_QP1   320
#define S0U     (U_MLP+U_QP1)     // 360
#define U_QP2   200
#define U_QR1   160
#define S1U     (U_QP2+U_QR1)     // 360
#define U_QR2   160               // S2
#define U_QK    440               // S3
#define U_QKR   828
#define U_AVG   256
#define S4U     (U_QKR+U_AVG)     // 1084
#define U_GATP  154               // S5
#define U_GR    166               // S6

__global__ void __launch_bounds__(256, 2) fused_k(
    const float* __restrict__ sc,  const float* __restrict__ bw,
    const float* __restrict__ ss,  const float* __restrict__ bsm,
    const float* __restrict__ qf,
    const float* __restrict__ Wm1, const float* __restrict__ bm1,
    const float* __restrict__ Wm2, const float* __restrict__ bm2,
    const float* __restrict__ Wvis,const float* __restrict__ bvis,
    const float* __restrict__ Wsem,const float* __restrict__ bsem,
    const float* __restrict__ Wq,  const float* __restrict__ Wk,
    const float* __restrict__ Wv,  const float* __restrict__ Wqs,
    const float* __restrict__ Wks, const float* __restrict__ Wfc,
    const float* __restrict__ temp, float* __restrict__ outL)
{
    extern __shared__ __align__(32) float sm[];
    const int NBLK = gridDim.x;
    const int t = threadIdx.x;
    const uint64_t pol = mkpolicy();
    int gen = 1;

    // ===== S0: MLP | qp1 (sc@Wq) =====
    for (int u = blockIdx.x; u < S0U; u += NBLK) {
        if (u < U_MLP) {
            int m0u = u * 4;
            for (int i = t; i < 4*SEM; i += 256)
                sm[i] = ss[(size_t)(m0u + i/SEM)*SEM + (i % SEM)];
            __syncthreads();
            for (int n = t; n < SEM; n += 256) {
                float a0 = bm1[n], a1 = a0, a2 = a0, a3 = a0;
                for (int k = 0; k < SEM; k++) {
                    float w = Wm1[(size_t)k*SEM + n];
                    a0 = fmaf(sm[0*SEM+k], w, a0); a1 = fmaf(sm[1*SEM+k], w, a1);
                    a2 = fmaf(sm[2*SEM+k], w, a2); a3 = fmaf(sm[3*SEM+k], w, a3);
                }
                sm[1280 + 0*SEM + n] = (a0 >= 0.f) ? a0 : 0.1f*a0;
                sm[1280 + 1*SEM + n] = (a1 >= 0.f) ? a1 : 0.1f*a1;
                sm[1280 + 2*SEM + n] = (a2 >= 0.f) ? a2 : 0.1f*a2;
                sm[1280 + 3*SEM + n] = (a3 >= 0.f) ? a3 : 0.1f*a3;
            }
            __syncthreads();
            for (int n = t; n < SEM; n += 256) {
                float a0 = bm2[n], a1 = a0, a2 = a0, a3 = a0;
                for (int k = 0; k < SEM; k++) {
                    float w = Wm2[(size_t)k*SEM + n];
                    a0 = fmaf(sm[1280+0*SEM+k], w, a0); a1 = fmaf(sm[1280+1*SEM+k], w, a1);
                    a2 = fmaf(sm[1280+2*SEM+k], w, a2); a3 = fmaf(sm[1280+3*SEM+k], w, a3);
                }
                g_scal[(size_t)(m0u+0)*SEM + n] = a0;
                g_scal[(size_t)(m0u+1)*SEM + n] = a1;
                g_scal[(size_t)(m0u+2)*SEM + n] = a2;
                g_scal[(size_t)(m0u+3)*SEM + n] = a3;
            }
            __syncthreads();
        } else {
            int uu = u - U_MLP;
            int z = uu & 7, r = uu >> 3;
            int nt = r & 7, mt = r >> 3;
            gemm_pipe<false>(sc, BTOT, FD, FD, Wq, Wq, FD, FD, FD, FD,
                g_part, (size_t)z*MNq, FD, mt*32, nt*128, z*4, z*4+4, sm);
        }
    }
    gsync(gen);

    // ===== S1: qp2 (s@Wqs) | qp1 reduce (slabs 0..7 -> g_q) =====
    for (int u = blockIdx.x; u < S1U; u += NBLK) {
        if (u < U_QP2) {
            int z = u % 5, r = u / 5;
            int nt = r & 7, mt = r >> 3;
            gemm_pipe<false>(g_scal, BTOT, SEM, SEM, Wqs, Wqs, FD, FD, FD, FD,
                g_part, (size_t)(8+z)*MNq, FD, mt*32, nt*128, z*2, z*2+2, sm);
        } else {
            size_t i4 = (size_t)(u - U_QP2)*256 + t;
            float4 v = make_float4(0,0,0,0);
#pragma unroll
            for (int z = 0; z < 8; z++) {
                float4 w = ((const float4*)g_part)[(size_t)z*(MNq/4) + i4];
                v.x+=w.x; v.y+=w.y; v.z+=w.z; v.w+=w.w;
            }
            ((float4*)g_q)[i4] = v;
        }
    }
    gsync(gen);

    // ===== S2: q final reduce (add qp2 slabs 8..12) =====
    for (int u = blockIdx.x; u < U_QR2; u += NBLK) {
        size_t i4 = (size_t)u*256 + t;
        float4 v = ((const float4*)g_q)[i4];
#pragma unroll
        for (int z = 8; z < 13; z++) {
            float4 w = ((const float4*)g_part)[(size_t)z*(MNq/4) + i4];
            v.x+=w.x; v.y+=w.y; v.z+=w.z; v.w+=w.w;
        }
        ((float4*)g_q)[i4] = v;
    }
    gsync(gen);

    // ===== S3: qk GEMM (q @ [Wk;Wks]^T, pipelined BTR) =====
    for (int u = blockIdx.x; u < U_QK; u += NBLK) {
        int z = u & 7, r = u >> 3;
        int nt = r % 11, mt = r / 11;
        gemm_pipe<true>(g_q, BTOT, FD, FD, Wk, Wks, FD, CATD, FD, FD,
            g_part, (size_t)z*SLABK, 1408, mt*32, nt*128, z*4, z*4+4, sm);
    }
    gsync(gen);

    // ===== S4: qk reduce (UNGATED) | avg partials (bank read #1, evict_last) =====
    for (int u = blockIdx.x; u < S4U; u += NBLK) {
        if (u < U_QKR) {
            size_t i = (size_t)u*256 + t;
            if (i < (size_t)MNk) {
                int m = (int)(i / CATD), n = (int)(i % CATD);
                float v = 0.f;
#pragma unroll
                for (int z = 0; z < 8; z++) v += g_part[(size_t)z*SLABK + (size_t)m*1408 + n];
                if (n < FD) g_qkg [(size_t)m*FD  + n]      = v;
                else        g_qksg[(size_t)m*SEM + (n-FD)] = v;
            }
        } else {
            int uu = u - U_QKR;
            int chunk = uu >> 6, r = uu & 63;
            int b = r >> 1, cpart = r & 1;
            int c4 = cpart*256 + t;
            if (c4 < CATD/4) {
                int c = c4*4;
                int n0 = chunk*128;
                float4 v = make_float4(0,0,0,0);
                if (c < FD) {
                    const float4* p = (const float4*)bw + ((size_t)b*NB + n0)*(FD/4) + c4;
#pragma unroll 16
                    for (int n = 0; n < 128; n++) {
                        float4 x = ldg_el(&p[(size_t)n*(FD/4)], pol);
                        v.x+=x.x; v.y+=x.y; v.z+=x.z; v.w+=x.w;
                    }
                } else {
                    const float4* p = (const float4*)(bsm + ((size_t)b*NB + n0)*SEM + (c-FD));
#pragma unroll 16
                    for (int n = 0; n < 128; n++) {
                        float4 x = ldg_el(&p[(size_t)n*(SEM/4)], pol);
                        v.x+=x.x; v.y+=x.y; v.z+=x.z; v.w+=x.w;
                    }
                }
                *(float4*)&g_avgp[(size_t)chunk*BS*CATD + (size_t)b*CATD + c] = v;
            }
        }
    }
    gsync(gen);

    // ===== S5: gates GEMM partials =====
    for (int u = blockIdx.x; u < U_GATP; u += NBLK) {
        int z = u % 14, nt = u / 14;
        gemm_w<true,false>(g_avgp, BS, CATD, CATD, 4, (size_t)BS*CATD, 1.f/NB, nullptr,
            Wvis, Wsem, FD, CATD, FD, SEM,
            g_part2, (size_t)z*SLABG, 1408, 0, nt*128, z*3, z*3+3, sm);
    }
    gsync(gen);

    // ===== S6: gates reduce =====
    for (int u = blockIdx.x; u < U_GR; u += NBLK) {
        size_t i = (size_t)u*256 + t;
        if (i < (size_t)BS*CATD) {
            int m = (int)(i / CATD), n = (int)(i % CATD);
            float v = 0.f;
#pragma unroll
            for (int z = 0; z < 14; z++) v += g_part2[(size_t)z*SLABG + (size_t)m*1408 + n];
            if (n < FD) {
                v += bvis[n];
                g_gv[(size_t)m*FD + n] = 1.f + 1.f/(1.f + __expf(-v));
            } else {
                v += bsem[n - FD];
                g_gs[(size_t)m*SEM + (n - FD)] = 1.f + 1.f/(1.f + __expf(-v));
            }
        }
    }
    gsync(gen);

    // ===== S7: scores (bank read #2 — should be L2-resident), gates fused =====
    for (int u = blockIdx.x; u < 256; u += NBLK) {
        int b = u >> 3, ch = u & 7;
        int w = t >> 5, lane = t & 31;
        int nbase = ch*64 + w*8;
        float acc[8][5];
#pragma unroll
        for (int j = 0; j < 8; j++)
#pragma unroll
            for (int p = 0; p < 5; p++) acc[j][p] = 0.f;
        const float4* qkg4 = (const float4*)g_qkg  + (size_t)b*NWAY*(FD/4);
        const float4* qks4 = (const float4*)g_qksg + (size_t)b*NWAY*(SEM/4);
        const float4* gv4  = (const float4*)g_gv   + (size_t)b*(FD/4);
        const float4* gs4  = (const float4*)g_gs   + (size_t)b*(SEM/4);
        const float4* bw4  = (const float4*)bw     + (size_t)b*NB*(FD/4);
        const float4* bs4  = (const float4*)bsm    + (size_t)b*NB*(SEM/4);
#pragma unroll
        for (int tt = 0; tt < 8; tt++) {
            int c = tt*32 + lane;
            float4 gc = gv4[c];
            float4 x[8];
#pragma unroll
            for (int j = 0; j < 8; j++)
                x[j] = ldg_el(&bw4[(size_t)(nbase+j)*(FD/4) + c], pol);
#pragma unroll
            for (int p = 0; p < 5; p++) {
                float4 qv = qkg4[p*(FD/4) + c];
                qv.x*=gc.x; qv.y*=gc.y; qv.z*=gc.z; qv.w*=gc.w;
#pragma unroll
                for (int j = 0; j < 8; j++) acc[j][p] += d4(x[j], qv);
            }
        }
#pragma unroll
        for (int tt = 0; tt < 3; tt++) {
            int c = tt*32 + lane;
            bool ok = c < (SEM/4);
            float4 gc = ok ? gs4[c] : make_float4(0,0,0,0);
            float4 x[8];
#pragma unroll
            for (int j = 0; j < 8; j++)
                x[j] = ok ? ldg_el(&bs4[(size_t)(nbase+j)*(SEM/4) + c], pol) : make_float4(0,0,0,0);
#pragma unroll
            for (int p = 0; p < 5; p++) {
                float4 qv = ok ? qks4[p*(SEM/4) + c] : make_float4(0,0,0,0);
                qv.x*=gc.x; qv.y*=gc.y; qv.z*=gc.z; qv.w*=gc.w;
#pragma unroll
                for (int j = 0; j < 8; j++) acc[j][p] += d4(x[j], qv);
            }
        }
#pragma unroll
        for (int off = 16; off; off >>= 1)
#pragma unroll
            for (int j = 0; j < 8; j++)
#pragma unroll
                for (int p = 0; p < 5; p++)
                    acc[j][p] += __shfl_xor_sync(0xffffffffu, acc[j][p], off);
#pragma unroll
        for (int j = 0; j < 8; j++)
            if (lane == j) {
                int n = nbase + j;
#pragma unroll
                for (int p = 0; p < 5; p++)
                    g_scr[(size_t)(b*NWAY+p)*NB + n] = acc[j][p] * (1.f/32.f);
            }
    }
    gsync(gen);

    // ===== S8: fused softmax + nway-avg attention + mix partials (bank read #3, L2) =====
    for (int u = blockIdx.x; u < 256; u += NBLK) {
        int b = u >> 3, chunk = u & 7;
        int n0 = chunk*64;
        int w = t >> 5, lane = t & 31;
        for (int i = t; i < NWAY*NB; i += 256)
            sm[i] = g_scr[(size_t)b*NWAY*NB + i];
        __syncthreads();
        float mx[5];
#pragma unroll
        for (int p = 0; p < 5; p++)
            mx[p] = fmaxf(sm[p*NB + t], sm[p*NB + 256 + t]);
#pragma unroll
        for (int off = 16; off; off >>= 1)
#pragma unroll
            for (int p = 0; p < 5; p++)
                mx[p] = fmaxf(mx[p], __shfl_xor_sync(0xffffffffu, mx[p], off));
        if (lane == 0)
#pragma unroll
            for (int p = 0; p < 5; p++) sm[2624 + w*5 + p] = mx[p];
        __syncthreads();
        if (t < 5) {
            float m = sm[2624 + t];
            for (int w2 = 1; w2 < 8; w2++) m = fmaxf(m, sm[2624 + w2*5 + t]);
            sm[2680 + t] = m;
        }
        __syncthreads();
        float sme[5];
#pragma unroll
        for (int p = 0; p < 5; p++) {
            float m = sm[2680 + p];
            sme[p] = __expf(sm[p*NB + t] - m) + __expf(sm[p*NB + 256 + t] - m);
        }
#pragma unroll
        for (int off = 16; off; off >>= 1)
#pragma unroll
            for (int p = 0; p < 5; p++)
                sme[p] += __shfl_xor_sync(0xffffffffu, sme[p], off);
        if (lane == 0)
#pragma unroll
            for (int p = 0; p < 5; p++) sm[2624 + w*5 + p] = sme[p];
        __syncthreads();
        if (t < 5) {
            float s = 0.f;
            for (int w2 = 0; w2 < 8; w2++) s += sm[2624 + w2*5 + t];
            sm[2688 + t] = 1.f / s;
        }
        __syncthreads();
        if (t < 64) {
            int n = n0 + t;
            float a = 0.f;
#pragma unroll
            for (int p = 0; p < 5; p++)
                a += __expf(sm[p*NB + n] - sm[2680 + p]) * sm[2688 + p];
            sm[2696 + t] = a * (1.f/NWAY);
        }
        __syncthreads();
        float4 acc = make_float4(0,0,0,0);
        const float4* p4 = (const float4*)bw + ((size_t)b*NB + n0)*(FD/4) + t;
#pragma unroll 16
        for (int r = 0; r < 64; r++) {
            float4 x = p4[(size_t)r*(FD/4)];
            float a = sm[2696 + r];
            acc.x = fmaf(x.x, a, acc.x); acc.y = fmaf(x.y, a, acc.y);
            acc.z = fmaf(x.z, a, acc.z); acc.w = fmaf(x.w, a, acc.w);
        }
        ((float4*)g_mixp)[(size_t)chunk*(SLABF/4) + (size_t)b*(FD/4) + t] = acc;
        __syncthreads();
    }
    gsync(gen);

    // ===== S9: fakev = (mixavg * gv) @ Wv, split-K 16 =====
    for (int u = blockIdx.x; u < 128; u += NBLK) {
        int z = u & 15, nt = u >> 4;
        gemm_w<true,true>(g_mixp, BS, FD, FD, 8, (size_t)SLABF, 1.f, g_gv,
            Wv, Wv, FD, FD, FD, FD,
            g_part, (size_t)z*SLABF, FD, 0, nt*128, z*2, z*2+2, sm);
    }
    gsync(gen);

    // ===== S10: fakefc = reduce(fakev) @ Wfc, split-K 16 =====
    for (int u = blockIdx.x; u < 128; u += NBLK) {
        int z = u & 15, nt = u >> 4;
        gemm_w<true,false>(g_part, BS, FD, FD, 16, (size_t)SLABF, 1.f, nullptr,
            Wfc, Wfc, FD, FD, FD, FD,
            g_part, (size_t)(16+z)*SLABF, FD, 0, nt*128, z*2, z*2+2, sm);
    }
    gsync(gen);

    // ===== S11: fake + norms + logits =====
    for (int u = blockIdx.x; u < BS*10; u += NBLK) {
        int b = u / 10, qc = u % 10;
        {
            const float4* sc4 = (const float4*)sc + (size_t)b*NWAY*(FD/4);
            float4 f = make_float4(0,0,0,0);
            float sq[6];
#pragma unroll
            for (int c = 0; c < NWAY; c++) {
                float4 o = sc4[c*(FD/4) + t];
                sq[c] = d4(o, o);
                f.x+=o.x; f.y+=o.y; f.z+=o.z; f.w+=o.w;
            }
            f.x*=0.2f; f.y*=0.2f; f.z*=0.2f; f.w*=0.2f;
#pragma unroll
            for (int z = 16; z < 32; z++) {
                float4 w2 = ((const float4*)g_part)[(size_t)z*(SLABF/4) + (size_t)b*(FD/4) + t];
                f.x+=w2.x; f.y+=w2.y; f.z+=w2.z; f.w+=w2.w;
            }
            ((float4*)sm)[t] = f;
            sq[5] = d4(f, f);
#pragma unroll
            for (int off = 16; off; off >>= 1)
#pragma unroll
                for (int r = 0; r < 6; r++)
                    sq[r] += __shfl_xor_sync(0xffffffffu, sq[r], off);
            int lane = t & 31, w = t >> 5;
            if (lane == 0)
#pragma unroll
                for (int r = 0; r < 6; r++) sm[1024 + w*6 + r] = sq[r];
            __syncthreads();
            if (t < 6) {
                float s = 0.f;
                for (int w2 = 0; w2 < 8; w2++) s += sm[1024 + w2*6 + t];
                sm[1072 + t] = 1.f / sqrtf(s);
            }
            __syncthreads();
        }
        {
            int w = t >> 5, lane = t & 31;
            int iq = qc*8 + w;
            if (iq < NQ) {
                const float4* q4  = (const float4*)qf + ((size_t)b*NQ + iq)*(FD/4);
                const float4* sc4 = (const float4*)sc + (size_t)b*NWAY*(FD/4);
                const float4* f4  = (const float4*)sm;
                float qq = 0.f, d[6] = {0,0,0,0,0,0};
                for (int i = lane; i < FD/4; i += 32) {
                    float4 x = q4[i];
                    qq += d4(x, x);
#pragma unroll
                    for (int r = 0; r < NWAY; r++) d[r] += d4(x, sc4[r*(FD/4) + i]);
                    d[5] += d4(x, f4[i]);
                }
#pragma unroll
                for (int off = 16; off; off >>= 1) {
                    qq += __shfl_xor_sync(0xffffffffu, qq, off);
#pragma unroll
                    for (int r = 0; r < 6; r++) d[r] += __shfl_xor_sync(0xffffffffu, d[r], off);
                }
                if (lane == 0) {
                    float s = temp[0] / sqrtf(qq);
                    float* o = outL + ((size_t)b*NQ + iq)*6;
#pragma unroll
                    for (int r = 0; r < 6; r++) o[r] = d[r] * s * sm[1072 + r];
                }
            }
        }
        __syncthreads();
    }
}

// ---------------- host ----------------
extern "C" void kernel_launch(void* const* d_in, const int* in_sizes, int n_in,
                              void* d_out, int out_size)
{
    const float* sc   = (const float*)d_in[0];
    const float* bw   = (const float*)d_in[1];
    const float* ss   = (const float*)d_in[2];
    const float* bsm  = (const float*)d_in[3];
    const float* qf   = (const float*)d_in[4];
    const float* Wm1  = (const float*)d_in[5];
    const float* bm1  = (const float*)d_in[6];
    const float* Wm2  = (const float*)d_in[7];
    const float* bm2  = (const float*)d_in[8];
    const float* Wvis = (const float*)d_in[9];
    const float* bvis = (const float*)d_in[10];
    const float* Wsem = (const float*)d_in[11];
    const float* bsem = (const float*)d_in[12];
    const float* Wq   = (const float*)d_in[13];
    const float* Wk   = (const float*)d_in[14];
    const float* Wv   = (const float*)d_in[15];
    const float* Wqs  = (const float*)d_in[16];
    const float* Wks  = (const float*)d_in[17];
    const float* Wfc  = (const float*)d_in[18];
    const float* temp = (const float*)d_in[19];
    float* out = (float*)d_out;

    const int smem_bytes = SMEMF * sizeof(float);  // 51200
    cudaFuncSetAttribute(fused_k, cudaFuncAttributeMaxDynamicSharedMemorySize, smem_bytes);

    int dev = 0;
    cudaGetDevice(&dev);
    int nsm = 148;
    cudaDeviceGetAttribute(&nsm, cudaDevAttrMultiProcessorCount, dev);
    int bpm = 1;
    cudaOccupancyMaxActiveBlocksPerMultiprocessor(&bpm, fused_k, 256, smem_bytes);
    if (bpm < 1) bpm = 1;
    int nblk = nsm * bpm;

    void* barp = nullptr;
    cudaGetSymbolAddress(&barp, g_barrier);
    cudaMemsetAsync(barp, 0, sizeof(unsigned int), 0);

    fused_k<<<nblk, 256, smem_bytes>>>(sc, bw, ss, bsm, qf, Wm1, bm1, Wm2, bm2,
                                       Wvis, bvis, Wsem, bsem, Wq, Wk, Wv, Wqs, Wks, Wfc,
                                       temp, out);
}

// round 12
// speedup vs baseline: 1.0855x; 1.0855x over previous
#include <cuda_runtime.h>
#include <mma.h>
#include <math.h>
#include <cstdint>

using namespace nvcuda;

#define FD    1024
#define SEM   300
#define NWAY  5
#define BS    32
#define NB    512
#define NQ    75
#define BTOT  (BS*NWAY)     // 160
#define CATD  (FD+SEM)      // 1324

#define MNq   (BTOT*FD)     // 163840
#define MNk   (BTOT*CATD)   // 211840
#define SLABK (BTOT*1408)   // padded qk partial slab
#define SLABG (BS*1408)
#define SLABF (BS*FD)       // 32768

#define SMEMF 12800         // dynamic smem floats (2 x 6400 gemm buffers)
#define BUFF  6400

// ---------------- scratch ----------------
__device__ __align__(32) float g_scal[BTOT*SEM];
__device__ __align__(32) float g_gv  [BS*FD];
__device__ __align__(32) float g_gs  [BS*SEM];
__device__ __align__(32) float g_q   [BTOT*FD];
__device__ __align__(32) float g_qkg [BTOT*FD];
__device__ __align__(32) float g_qksg[BTOT*SEM];
__device__ __align__(32) float g_scr [BTOT*NB];
__device__ __align__(32) float g_avgp[4*BS*CATD];
__device__ __align__(32) float g_mixp[8*SLABF];
__device__ __align__(32) float g_part [16*MNq];
__device__ __align__(32) float g_part2[14*SLABG];
__device__ unsigned int g_barrier;

// ---------------- software grid barrier ----------------
__device__ __forceinline__ void gsync(int &gen)
{
    __syncthreads();
    if (threadIdx.x == 0) {
        __threadfence();
        atomicAdd(&g_barrier, 1u);
        unsigned target = (unsigned)gridDim.x * (unsigned)gen;
        unsigned v;
        do {
            asm volatile("ld.acquire.gpu.u32 %0, [%1];" : "=r"(v) : "l"(&g_barrier) : "memory");
            if (v >= target) break;
            __nanosleep(32);
        } while (true);
    }
    __syncthreads();
    gen++;
}

__device__ __forceinline__ float d4(float4 a, float4 b)
{ return a.x*b.x + a.y*b.y + a.z*b.z + a.w*b.w; }

__device__ __forceinline__ uint64_t mkpolicy()
{
    uint64_t p;
    asm volatile("createpolicy.fractional.L2::evict_last.b64 %0, 1.0;" : "=l"(p));
    return p;
}

__device__ __forceinline__ float4 ldg_el(const float4* p, uint64_t pol)
{
    float4 v;
    asm volatile("ld.global.L2::cache_hint.v4.f32 {%0,%1,%2,%3}, [%4], %5;"
        : "=f"(v.x), "=f"(v.y), "=f"(v.z), "=f"(v.w) : "l"(p), "l"(pol));
    return v;
}

__device__ __forceinline__ void cp16(uint32_t saddr, const void* g, bool pred)
{
    asm volatile("cp.async.ca.shared.global [%0], [%1], 16, %2;"
        :: "r"(saddr), "l"(g), "r"(pred ? 16 : 0));
}

typedef wmma::fragment<wmma::matrix_a, 16,16,8, wmma::precision::tf32, wmma::row_major> FragA;
typedef wmma::fragment<wmma::matrix_b, 16,16,8, wmma::precision::tf32, wmma::row_major> FragBR;
typedef wmma::fragment<wmma::matrix_b, 16,16,8, wmma::precision::tf32, wmma::col_major> FragBC;
typedef wmma::fragment<wmma::accumulator, 16,16,8, float> FragC;

template<class F>
__device__ __forceinline__ void split_frag(F& hi, F& lo)
{
#pragma unroll
    for (int i = 0; i < hi.num_elements; i++) {
        float r = hi.x[i];
        float h = wmma::__float_to_tf32(r);
        hi.x[i] = h;
        lo.x[i] = wmma::__float_to_tf32(r - h);
    }
}

template<bool BTR>
__device__ __forceinline__ void mma_tile(float* As, float* Bs, int mrow, int nq,
                                         FragC& c0, FragC& c1)
{
#pragma unroll
    for (int kk = 0; kk < 32; kk += 8) {
        FragA ah, al;
        wmma::load_matrix_sync(ah, As + mrow*16*40 + kk, 40);
        split_frag(ah, al);
        if (!BTR) {
            FragBR b0h,b0l,b1h,b1l;
            wmma::load_matrix_sync(b0h, Bs + kk*136 + nq*32, 136);
            wmma::load_matrix_sync(b1h, Bs + kk*136 + nq*32 + 16, 136);
            split_frag(b0h, b0l); split_frag(b1h, b1l);
            wmma::mma_sync(c0, ah, b0h, c0);
            wmma::mma_sync(c0, ah, b0l, c0);
            wmma::mma_sync(c0, al, b0h, c0);
            wmma::mma_sync(c1, ah, b1h, c1);
            wmma::mma_sync(c1, ah, b1l, c1);
            wmma::mma_sync(c1, al, b1h, c1);
        } else {
            FragBC b0h,b0l,b1h,b1l;
            wmma::load_matrix_sync(b0h, Bs + (nq*32)*40 + kk, 40);
            wmma::load_matrix_sync(b1h, Bs + (nq*32+16)*40 + kk, 40);
            split_frag(b0h, b0l); split_frag(b1h, b1l);
            wmma::mma_sync(c0, ah, b0h, c0);
            wmma::mma_sync(c0, ah, b0l, c0);
            wmma::mma_sync(c0, al, b0h, c0);
            wmma::mma_sync(c1, ah, b1h, c1);
            wmma::mma_sync(c1, ah, b1l, c1);
            wmma::mma_sync(c1, al, b1h, c1);
        }
    }
}

template<bool BTR>
__device__ __forceinline__ void gemm_pipe(
    const float* __restrict__ A, int M, int K, int lda,
    const float* __restrict__ B1, const float* __restrict__ B2,
    int N1, int N, int ldb1, int ldb2,
    float* __restrict__ part, size_t slab, int ldp,
    int m0, int n0, int kt0, int kt1, float* __restrict__ smbase)
{
    const int t = threadIdx.x;
    const int warp = t >> 5, mrow = warp >> 2, nq = warp & 3;
    FragC c0, c1;
    wmma::fill_fragment(c0, 0.f);
    wmma::fill_fragment(c1, 0.f);

    auto issue = [&](int kt, int bufi) {
        float* As = smbase + bufi*BUFF;
        float* Bs = As + 1280;
        int k0 = kt*32;
        {
            int mm = t >> 3, kq = t & 7;
            int mg = m0 + mm, kg = k0 + kq*4;
            bool ok = (mg < M) && (kg < K);
            uint32_t sa = (uint32_t)__cvta_generic_to_shared(&As[mm*40 + kq*4]);
            cp16(sa, &A[(size_t)mg*lda + kg], ok);
        }
        if (!BTR) {
            int kk = t >> 3, cc = t & 7;
            int kg = k0 + kk;
#pragma unroll
            for (int j = 0; j < 4; j++) {
                int nn = (cc + 8*j)*4;
                int ng = n0 + nn;
                bool ok = (kg < K) && (ng < N);
                const float* g = (ng < N1) ? &B1[(size_t)kg*ldb1 + ng]
                                           : &B2[(size_t)kg*ldb2 + (ng - N1)];
                uint32_t sa = (uint32_t)__cvta_generic_to_shared(&Bs[kk*136 + nn]);
                cp16(sa, g, ok);
            }
        } else {
            int n = t >> 1, half = t & 1;
            int ng = n0 + n;
            bool okrow = ng < N;
            const float* brow = okrow ? ((ng < N1) ? &B1[(size_t)ng*ldb1]
                                                   : &B2[(size_t)(ng-N1)*ldb2]) : B1;
#pragma unroll
            for (int j = 0; j < 4; j++) {
                int kg = k0 + half*16 + j*4;
                bool ok = okrow && (kg < K);
                uint32_t sa = (uint32_t)__cvta_generic_to_shared(&Bs[n*40 + half*16 + j*4]);
                cp16(sa, &brow[kg], ok);
            }
        }
        asm volatile("cp.async.commit_group;");
    };

    issue(kt0, 0);
    for (int kt = kt0; kt < kt1; kt++) {
        int bufi = (kt - kt0) & 1;
        bool more = (kt + 1 < kt1);
        if (more) issue(kt + 1, bufi ^ 1);
        if (more) asm volatile("cp.async.wait_group 1;");
        else      asm volatile("cp.async.wait_group 0;");
        __syncthreads();
        float* As = smbase + bufi*BUFF;
        mma_tile<BTR>(As, As + 1280, mrow, nq, c0, c1);
        __syncthreads();
    }
    float* cb = part + slab + (size_t)(m0 + mrow*16)*ldp + n0 + nq*32;
    wmma::store_matrix_sync(cb,      c0, ldp, wmma::mem_row_major);
    wmma::store_matrix_sync(cb + 16, c1, ldp, wmma::mem_row_major);
}

template<bool REDA, bool GATEA>
__device__ __forceinline__ void gemm_w(
    const float* __restrict__ A, int M, int K, int lda,
    int Zred, size_t slabA, float ascale, const float* __restrict__ gateA,
    const float* __restrict__ B1, const float* __restrict__ B2,
    int N1, int N, int ldb1, int ldb2,
    float* __restrict__ part, size_t slab, int ldp,
    int m0, int n0, int kt0, int kt1, float* __restrict__ smbase)
{
    const int t = threadIdx.x;
    const int warp = t >> 5, mrow = warp >> 2, nq = warp & 3;
    float* As = smbase;
    float* Bs = smbase + 1280;
    FragC c0, c1;
    wmma::fill_fragment(c0, 0.f);
    wmma::fill_fragment(c1, 0.f);

    for (int kt = kt0; kt < kt1; kt++) {
        int k0 = kt*32;
        {
            int mm = t >> 3, kq = (t & 7)*4;
            int mg = m0 + mm, kg = k0 + kq;
            float4 v = make_float4(0,0,0,0);
            if (mg < M && kg + 3 < K) {
                if (REDA) {
                    for (int z = 0; z < Zred; z++) {
                        float4 w = *(const float4*)&A[(size_t)z*slabA + (size_t)mg*lda + kg];
                        v.x+=w.x; v.y+=w.y; v.z+=w.z; v.w+=w.w;
                    }
                } else v = *(const float4*)&A[(size_t)mg*lda + kg];
                v.x*=ascale; v.y*=ascale; v.z*=ascale; v.w*=ascale;
                if (GATEA) {
                    float4 g = *(const float4*)&gateA[(size_t)mg*lda + kg];
                    v.x*=g.x; v.y*=g.y; v.z*=g.z; v.w*=g.w;
                }
            } else if (mg < M) {
                float tmp[4] = {0,0,0,0};
                for (int j = 0; j < 4; j++) {
                    int k2 = kg + j;
                    if (k2 < K) {
                        float s = 0.f;
                        if (REDA) { for (int z=0; z<Zred; z++) s += A[(size_t)z*slabA + (size_t)mg*lda + k2]; }
                        else s = A[(size_t)mg*lda + k2];
                        s *= ascale;
                        if (GATEA) s *= gateA[(size_t)mg*lda + k2];
                        tmp[j] = s;
                    }
                }
                v = make_float4(tmp[0],tmp[1],tmp[2],tmp[3]);
            }
            *(float4*)&As[ (t>>3)*40 + (t&7)*4 ] = v;
        }
        {
            int kk = t >> 3, cc = t & 7;
            int kg = k0 + kk;
#pragma unroll
            for (int j = 0; j < 4; j++) {
                int nn = (cc + 8*j)*4;
                int ng = n0 + nn;
                float4 v = make_float4(0,0,0,0);
                if (kg < K && ng < N) {
                    if (ng < N1) v = *(const float4*)&B1[(size_t)kg*ldb1 + ng];
                    else         v = *(const float4*)&B2[(size_t)kg*ldb2 + (ng-N1)];
                }
                *(float4*)&Bs[kk*136 + nn] = v;
            }
        }
        __syncthreads();
        mma_tile<false>(As, Bs, mrow, nq, c0, c1);
        __syncthreads();
    }
    float* cb = part + slab + (size_t)(m0 + mrow*16)*ldp + n0 + nq*32;
    wmma::store_matrix_sync(cb,      c0, ldp, wmma::mem_row_major);
    wmma::store_matrix_sync(cb + 16, c1, ldp, wmma::mem_row_major);
}

// stage unit counts (R9 layout: avg next to consumers, static scheduling)
#define U_MLP   40
#define U_QP1   320
#define S0U     (U_MLP+U_QP1)     // 360
#define U_QP2   200
#define U_AVG   256
#define S1U     (U_QP2+U_AVG)     // 456
#define U_QR    160
#define U_GATP  154
#define S2U     (U_QR+U_GATP)     // 314
#define U_GR    166
#define U_QK    440
#define S3U     (U_GR+U_QK)       // 606

__global__ void __launch_bounds__(256, 3) fused_k(
    const float* __restrict__ sc,  const float* __restrict__ bw,
    const float* __restrict__ ss,  const float* __restrict__ bsm,
    const float* __restrict__ qf,
    const float* __restrict__ Wm1, const float* __restrict__ bm1,
    const float* __restrict__ Wm2, const float* __restrict__ bm2,
    const float* __restrict__ Wvis,const float* __restrict__ bvis,
    const float* __restrict__ Wsem,const float* __restrict__ bsem,
    const float* __restrict__ Wq,  const float* __restrict__ Wk,
    const float* __restrict__ Wv,  const float* __restrict__ Wqs,
    const float* __restrict__ Wks, const float* __restrict__ Wfc,
    const float* __restrict__ temp, float* __restrict__ outL)
{
    extern __shared__ __align__(32) float sm[];
    const int NBLK = gridDim.x;
    const int t = threadIdx.x;
    const uint64_t pol = mkpolicy();
    int gen = 1;

    // ===== S0: MLP | qp1 (sc@Wq, pipelined) =====
    for (int u = blockIdx.x; u < S0U; u += NBLK) {
        if (u < U_MLP) {
            int m0u = u * 4;
            for (int i = t; i < 4*SEM; i += 256)
                sm[i] = ss[(size_t)(m0u + i/SEM)*SEM + (i % SEM)];
            __syncthreads();
            for (int n = t; n < SEM; n += 256) {
                float a0 = bm1[n], a1 = a0, a2 = a0, a3 = a0;
                for (int k = 0; k < SEM; k++) {
                    float w = Wm1[(size_t)k*SEM + n];
                    a0 = fmaf(sm[0*SEM+k], w, a0); a1 = fmaf(sm[1*SEM+k], w, a1);
                    a2 = fmaf(sm[2*SEM+k], w, a2); a3 = fmaf(sm[3*SEM+k], w, a3);
                }
                sm[1280 + 0*SEM + n] = (a0 >= 0.f) ? a0 : 0.1f*a0;
                sm[1280 + 1*SEM + n] = (a1 >= 0.f) ? a1 : 0.1f*a1;
                sm[1280 + 2*SEM + n] = (a2 >= 0.f) ? a2 : 0.1f*a2;
                sm[1280 + 3*SEM + n] = (a3 >= 0.f) ? a3 : 0.1f*a3;
            }
            __syncthreads();
            for (int n = t; n < SEM; n += 256) {
                float a0 = bm2[n], a1 = a0, a2 = a0, a3 = a0;
                for (int k = 0; k < SEM; k++) {
                    float w = Wm2[(size_t)k*SEM + n];
                    a0 = fmaf(sm[1280+0*SEM+k], w, a0); a1 = fmaf(sm[1280+1*SEM+k], w, a1);
                    a2 = fmaf(sm[1280+2*SEM+k], w, a2); a3 = fmaf(sm[1280+3*SEM+k], w, a3);
                }
                g_scal[(size_t)(m0u+0)*SEM + n] = a0;
                g_scal[(size_t)(m0u+1)*SEM + n] = a1;
                g_scal[(size_t)(m0u+2)*SEM + n] = a2;
                g_scal[(size_t)(m0u+3)*SEM + n] = a3;
            }
            __syncthreads();
        } else {
            int uu = u - U_MLP;
            int z = uu & 7, r = uu >> 3;
            int nt = r & 7, mt = r >> 3;
            gemm_pipe<false>(sc, BTOT, FD, FD, Wq, Wq, FD, FD, FD, FD,
                g_part, (size_t)z*MNq, FD, mt*32, nt*128, z*4, z*4+4, sm);
        }
    }
    gsync(gen);

    // ===== S1: qp2 (s@Wqs, pipelined) | avg partials (evict_last) =====
    for (int u = blockIdx.x; u < S1U; u += NBLK) {
        if (u < U_QP2) {
            int z = u % 5, r = u / 5;
            int nt = r & 7, mt = r >> 3;
            gemm_pipe<false>(g_scal, BTOT, SEM, SEM, Wqs, Wqs, FD, FD, FD, FD,
                g_part, (size_t)(8+z)*MNq, FD, mt*32, nt*128, z*2, z*2+2, sm);
        } else {
            int uu = u - U_QP2;
            int chunk = uu >> 6, r = uu & 63;
            int b = r >> 1, cpart = r & 1;
            int c4 = cpart*256 + t;
            if (c4 < CATD/4) {
                int c = c4*4;
                int n0 = chunk*128;
                float4 v = make_float4(0,0,0,0);
                if (c < FD) {
                    const float4* p = (const float4*)bw + ((size_t)b*NB + n0)*(FD/4) + c4;
#pragma unroll 16
                    for (int n = 0; n < 128; n++) {
                        float4 x = ldg_el(&p[(size_t)n*(FD/4)], pol);
                        v.x+=x.x; v.y+=x.y; v.z+=x.z; v.w+=x.w;
                    }
                } else {
                    const float4* p = (const float4*)(bsm + ((size_t)b*NB + n0)*SEM + (c-FD));
#pragma unroll 16
                    for (int n = 0; n < 128; n++) {
                        float4 x = ldg_el(&p[(size_t)n*(SEM/4)], pol);
                        v.x+=x.x; v.y+=x.y; v.z+=x.z; v.w+=x.w;
                    }
                }
                *(float4*)&g_avgp[(size_t)chunk*BS*CATD + (size_t)b*CATD + c] = v;
            }
        }
    }
    gsync(gen);

    // ===== S2: q reduce | gates GEMM partials =====
    for (int u = blockIdx.x; u < S2U; u += NBLK) {
        if (u < U_QR) {
            size_t i4 = (size_t)u*256 + t;
            float4 v = make_float4(0,0,0,0);
#pragma unroll
            for (int z = 0; z < 13; z++) {
                float4 w = ((const float4*)g_part)[(size_t)z*(MNq/4) + i4];
                v.x+=w.x; v.y+=w.y; v.z+=w.z; v.w+=w.w;
            }
            ((float4*)g_q)[i4] = v;
        } else {
            int uu = u - U_QR;
            int z = uu % 14, nt = uu / 14;
            gemm_w<true,false>(g_avgp, BS, CATD, CATD, 4, (size_t)BS*CATD, 1.f/NB, nullptr,
                Wvis, Wsem, FD, CATD, FD, SEM,
                g_part2, (size_t)z*SLABG, 1408, 0, nt*128, z*3, z*3+3, sm);
        }
    }
    gsync(gen);

    // ===== S3: gates reduce | qk GEMM =====
    for (int u = blockIdx.x; u < S3U; u += NBLK) {
        if (u < U_GR) {
            size_t i = (size_t)u*256 + t;
            if (i < (size_t)BS*CATD) {
                int m = (int)(i / CATD), n = (int)(i % CATD);
                float v = 0.f;
#pragma unroll
                for (int z = 0; z < 14; z++) v += g_part2[(size_t)z*SLABG + (size_t)m*1408 + n];
                if (n < FD) {
                    v += bvis[n];
                    g_gv[(size_t)m*FD + n] = 1.f + 1.f/(1.f + __expf(-v));
                } else {
                    v += bsem[n - FD];
                    g_gs[(size_t)m*SEM + (n - FD)] = 1.f + 1.f/(1.f + __expf(-v));
                }
            }
        } else {
            int uu = u - U_GR;
            int z = uu & 7, r = uu >> 3;
            int nt = r % 11, mt = r / 11;
            gemm_pipe<true>(g_q, BTOT, FD, FD, Wk, Wks, FD, CATD, FD, FD,
                g_part, (size_t)z*SLABK, 1408, mt*32, nt*128, z*4, z*4+4, sm);
        }
    }
    gsync(gen);

    // ===== S4: qk reduce * gates =====
    for (int u = blockIdx.x; u < 828; u += NBLK) {
        size_t i = (size_t)u*256 + t;
        if (i < (size_t)MNk) {
            int m = (int)(i / CATD), n = (int)(i % CATD);
            float v = 0.f;
#pragma unroll
            for (int z = 0; z < 8; z++) v += g_part[(size_t)z*SLABK + (size_t)m*1408 + n];
            int b = m / NWAY;
            if (n < FD) g_qkg [(size_t)m*FD  + n]      = v * g_gv[(size_t)b*FD  + n];
            else        g_qksg[(size_t)m*SEM + (n-FD)] = v * g_gs[(size_t)b*SEM + (n-FD)];
        }
    }
    gsync(gen);

    // ===== S5: scores (4 rows per warp) =====
    for (int u = blockIdx.x; u < 512; u += NBLK) {
        int b = u / 16, ch = u % 16;
        int w = t >> 5, lane = t & 31;
        int nbase = ch*32 + w*4;
        float acc[4][5];
#pragma unroll
        for (int j = 0; j < 4; j++)
#pragma unroll
            for (int p = 0; p < 5; p++) acc[j][p] = 0.f;
        const float4* qkg4 = (const float4*)g_qkg  + (size_t)b*NWAY*(FD/4);
        const float4* qks4 = (const float4*)g_qksg + (size_t)b*NWAY*(SEM/4);
        const float4* bw4  = (const float4*)bw     + (size_t)b*NB*(FD/4);
        const float4* bs4  = (const float4*)bsm    + (size_t)b*NB*(SEM/4);
#pragma unroll
        for (int tt = 0; tt < 8; tt++) {
            int c = tt*32 + lane;
            float4 qv[5];
#pragma unroll
            for (int p = 0; p < 5; p++) qv[p] = qkg4[p*(FD/4) + c];
#pragma unroll
            for (int j = 0; j < 4; j++) {
                float4 x = ldg_el(&bw4[(size_t)(nbase+j)*(FD/4) + c], pol);
#pragma unroll
                for (int p = 0; p < 5; p++) acc[j][p] += d4(x, qv[p]);
            }
        }
#pragma unroll
        for (int tt = 0; tt < 3; tt++) {
            int c = tt*32 + lane;
            bool ok = c < (SEM/4);
            float4 qv[5];
#pragma unroll
            for (int p = 0; p < 5; p++)
                qv[p] = ok ? qks4[p*(SEM/4) + c] : make_float4(0,0,0,0);
#pragma unroll
            for (int j = 0; j < 4; j++) {
                float4 x = ok ? ldg_el(&bs4[(size_t)(nbase+j)*(SEM/4) + c], pol) : make_float4(0,0,0,0);
#pragma unroll
                for (int p = 0; p < 5; p++) acc[j][p] += d4(x, qv[p]);
            }
        }
#pragma unroll
        for (int off = 16; off; off >>= 1)
#pragma unroll
            for (int j = 0; j < 4; j++)
#pragma unroll
                for (int p = 0; p < 5; p++)
                    acc[j][p] += __shfl_xor_sync(0xffffffffu, acc[j][p], off);
#pragma unroll
        for (int j = 0; j < 4; j++)
            if (lane == j) {
                int n = nbase + j;
#pragma unroll
                for (int p = 0; p < 5; p++)
                    g_scr[(size_t)(b*NWAY+p)*NB + n] = acc[j][p] * (1.f/32.f);
            }
    }
    gsync(gen);

    // ===== S6: fused softmax + nway-avg attention + mix partials =====
    for (int u = blockIdx.x; u < 256; u += NBLK) {
        int b = u >> 3, chunk = u & 7;
        int n0 = chunk*64;
        int w = t >> 5, lane = t & 31;
        for (int i = t; i < NWAY*NB; i += 256)
            sm[i] = g_scr[(size_t)b*NWAY*NB + i];
        __syncthreads();
        float mx[5];
#pragma unroll
        for (int p = 0; p < 5; p++)
            mx[p] = fmaxf(sm[p*NB + t], sm[p*NB + 256 + t]);
#pragma unroll
        for (int off = 16; off; off >>= 1)
#pragma unroll
            for (int p = 0; p < 5; p++)
                mx[p] = fmaxf(mx[p], __shfl_xor_sync(0xffffffffu, mx[p], off));
        if (lane == 0)
#pragma unroll
            for (int p = 0; p < 5; p++) sm[2624 + w*5 + p] = mx[p];
        __syncthreads();
        if (t < 5) {
            float m = sm[2624 + t];
            for (int w2 = 1; w2 < 8; w2++) m = fmaxf(m, sm[2624 + w2*5 + t]);
            sm[2680 + t] = m;
        }
        __syncthreads();
        float sme[5];
#pragma unroll
        for (int p = 0; p < 5; p++) {
            float m = sm[2680 + p];
            sme[p] = __expf(sm[p*NB + t] - m) + __expf(sm[p*NB + 256 + t] - m);
        }
#pragma unroll
        for (int off = 16; off; off >>= 1)
#pragma unroll
            for (int p = 0; p < 5; p++)
                sme[p] += __shfl_xor_sync(0xffffffffu, sme[p], off);
        if (lane == 0)
#pragma unroll
            for (int p = 0; p < 5; p++) sm[2624 + w*5 + p] = sme[p];
        __syncthreads();
        if (t < 5) {
            float s = 0.f;
            for (int w2 = 0; w2 < 8; w2++) s += sm[2624 + w2*5 + t];
            sm[2688 + t] = 1.f / s;
        }
        __syncthreads();
        if (t < 64) {
            int n = n0 + t;
            float a = 0.f;
#pragma unroll
            for (int p = 0; p < 5; p++)
                a += __expf(sm[p*NB + n] - sm[2680 + p]) * sm[2688 + p];
            sm[2696 + t] = a * (1.f/NWAY);
        }
        __syncthreads();
        float4 acc = make_float4(0,0,0,0);
        const float4* p4 = (const float4*)bw + ((size_t)b*NB + n0)*(FD/4) + t;
#pragma unroll 16
        for (int r = 0; r < 64; r++) {
            float4 x = p4[(size_t)r*(FD/4)];
            float a = sm[2696 + r];
            acc.x = fmaf(x.x, a, acc.x); acc.y = fmaf(x.y, a, acc.y);
            acc.z = fmaf(x.z, a, acc.z); acc.w = fmaf(x.w, a, acc.w);
        }
        ((float4*)g_mixp)[(size_t)chunk*(SLABF/4) + (size_t)b*(FD/4) + t] = acc;
        __syncthreads();
    }
    gsync(gen);

    // ===== S7: fakev = (mixavg * gv) @ Wv, split-K 16 =====
    for (int u = blockIdx.x; u < 128; u += NBLK) {
        int z = u & 15, nt = u >> 4;
        gemm_w<true,true>(g_mixp, BS, FD, FD, 8, (size_t)SLABF, 1.f, g_gv,
            Wv, Wv, FD, FD, FD, FD,
            g_part, (size_t)z*SLABF, FD, 0, nt*128, z*2, z*2+2, sm);
    }
    gsync(gen);

    // ===== S8: fakefc = reduce(fakev) @ Wfc, split-K 16 =====
    for (int u = blockIdx.x; u < 128; u += NBLK) {
        int z = u & 15, nt = u >> 4;
        gemm_w<true,false>(g_part, BS, FD, FD, 16, (size_t)SLABF, 1.f, nullptr,
            Wfc, Wfc, FD, FD, FD, FD,
            g_part, (size_t)(16+z)*SLABF, FD, 0, nt*128, z*2, z*2+2, sm);
    }
    gsync(gen);

    // ===== S9: fake + norms + logits =====
    for (int u = blockIdx.x; u < BS*10; u += NBLK) {
        int b = u / 10, qc = u % 10;
        {
            const float4* sc4 = (const float4*)sc + (size_t)b*NWAY*(FD/4);
            float4 f = make_float4(0,0,0,0);
            float sq[6];
#pragma unroll
            for (int c = 0; c < NWAY; c++) {
                float4 o = sc4[c*(FD/4) + t];
                sq[c] = d4(o, o);
                f.x+=o.x; f.y+=o.y; f.z+=o.z; f.w+=o.w;
            }
            f.x*=0.2f; f.y*=0.2f; f.z*=0.2f; f.w*=0.2f;
#pragma unroll
            for (int z = 16; z < 32; z++) {
                float4 w2 = ((const float4*)g_part)[(size_t)z*(SLABF/4) + (size_t)b*(FD/4) + t];
                f.x+=w2.x; f.y+=w2.y; f.z+=w2.z; f.w+=w2.w;
            }
            ((float4*)sm)[t] = f;
            sq[5] = d4(f, f);
#pragma unroll
            for (int off = 16; off; off >>= 1)
#pragma unroll
                for (int r = 0; r < 6; r++)
                    sq[r] += __shfl_xor_sync(0xffffffffu, sq[r], off);
            int lane = t & 31, w = t >> 5;
            if (lane == 0)
#pragma unroll
                for (int r = 0; r < 6; r++) sm[1024 + w*6 + r] = sq[r];
            __syncthreads();
            if (t < 6) {
                float s = 0.f;
                for (int w2 = 0; w2 < 8; w2++) s += sm[1024 + w2*6 + t];
                sm[1072 + t] = 1.f / sqrtf(s);
            }
            __syncthreads();
        }
        {
            int w = t >> 5, lane = t & 31;
            int iq = qc*8 + w;
            if (iq < NQ) {
                const float4* q4  = (const float4*)qf + ((size_t)b*NQ + iq)*(FD/4);
                const float4* sc4 = (const float4*)sc + (size_t)b*NWAY*(FD/4);
                const float4* f4  = (const float4*)sm;
                float qq = 0.f, d[6] = {0,0,0,0,0,0};
                for (int i = lane; i < FD/4; i += 32) {
                    float4 x = q4[i];
                    qq += d4(x, x);
#pragma unroll
                    for (int r = 0; r < NWAY; r++) d[r] += d4(x, sc4[r*(FD/4) + i]);
                    d[5] += d4(x, f4[i]);
                }
#pragma unroll
                for (int off = 16; off; off >>= 1) {
                    qq += __shfl_xor_sync(0xffffffffu, qq, off);
#pragma unroll
                    for (int r = 0; r < 6; r++) d[r] += __shfl_xor_sync(0xffffffffu, d[r], off);
                }
                if (lane == 0) {
                    float s = temp[0] / sqrtf(qq);
                    float* o = outL + ((size_t)b*NQ + iq)*6;
#pragma unroll
                    for (int r = 0; r < 6; r++) o[r] = d[r] * s * sm[1072 + r];
                }
            }
        }
        __syncthreads();
    }
}

// ---------------- host ----------------
extern "C" void kernel_launch(void* const* d_in, const int* in_sizes, int n_in,
                              void* d_out, int out_size)
{
    const float* sc   = (const float*)d_in[0];
    const float* bw   = (const float*)d_in[1];
    const float* ss   = (const float*)d_in[2];
    const float* bsm  = (const float*)d_in[3];
    const float* qf   = (const float*)d_in[4];
    const float* Wm1  = (const float*)d_in[5];
    const float* bm1  = (const float*)d_in[6];
    const float* Wm2  = (const float*)d_in[7];
    const float* bm2  = (const float*)d_in[8];
    const float* Wvis = (const float*)d_in[9];
    const float* bvis = (const float*)d_in[10];
    const float* Wsem = (const float*)d_in[11];
    const float* bsem = (const float*)d_in[12];
    const float* Wq   = (const float*)d_in[13];
    const float* Wk   = (const float*)d_in[14];
    const float* Wv   = (const float*)d_in[15];
    const float* Wqs  = (const float*)d_in[16];
    const float* Wks  = (const float*)d_in[17];
    const float* Wfc  = (const float*)d_in[18];
    const float* temp = (const float*)d_in[19];
    float* out = (float*)d_out;

    const int smem_bytes = SMEMF * sizeof(float);  // 51200
    cudaFuncSetAttribute(fused_k, cudaFuncAttributeMaxDynamicSharedMemorySize, smem_bytes);

    int dev = 0;
    cudaGetDevice(&dev);
    int nsm = 148;
    cudaDeviceGetAttribute(&nsm, cudaDevAttrMultiProcessorCount, dev);
    int bpm = 1;
    cudaOccupancyMaxActiveBlocksPerMultiprocessor(&bpm, fused_k, 256, smem_bytes);
    if (bpm < 1) bpm = 1;
    int nblk = nsm * bpm;

    void* barp = nullptr;
    cudaGetSymbolAddress(&barp, g_barrier);
    cudaMemsetAsync(barp, 0, sizeof(unsigned int), 0);

    fused_k<<<nblk, 256, smem_bytes>>>(sc, bw, ss, bsm, qf, Wm1, bm1, Wm2, bm2,
                                       Wvis, bvis, Wsem, bsem, Wq, Wk, Wv, Wqs, Wks, Wfc,
                                       temp, out);
}

// round 13
// speedup vs baseline: 1.1153x; 1.0274x over previous
#include <cuda_runtime.h>
#include <mma.h>
#include <math.h>
#include <cstdint>

using namespace nvcuda;

#define FD    1024
#define SEM   300
#define NWAY  5
#define BS    32
#define NB    512
#define NQ    75
#define BTOT  (BS*NWAY)     // 160
#define CATD  (FD+SEM)      // 1324

#define MNq   (BTOT*FD)     // 163840
#define MNk   (BTOT*CATD)   // 211840
#define SLABK (BTOT*1408)   // padded qk partial slab
#define SLABG (BS*1408)
#define SLABF (BS*FD)       // 32768

#define SMEMF 12800         // dynamic smem floats (2 x 6400 gemm buffers)
#define BUFF  6400

// ---------------- scratch ----------------
__device__ __align__(32) float g_scal[BTOT*SEM];
__device__ __align__(32) float g_gv  [BS*FD];
__device__ __align__(32) float g_gs  [BS*SEM];
__device__ __align__(32) float g_q   [BTOT*FD];
__device__ __align__(32) float g_qkg [BTOT*FD];
__device__ __align__(32) float g_qksg[BTOT*SEM];
__device__ __align__(32) float g_scr [BTOT*NB];
__device__ __align__(32) float g_avgp[4*BS*CATD];
__device__ __align__(32) float g_mixp[16*SLABF];
__device__ __align__(32) float g_part [16*MNq];
__device__ __align__(32) float g_part2[14*SLABG];
__device__ unsigned int g_barrier;

// ---------------- software grid barrier ----------------
__device__ __forceinline__ void gsync(int &gen)
{
    __syncthreads();
    if (threadIdx.x == 0) {
        __threadfence();
        atomicAdd(&g_barrier, 1u);
        unsigned target = (unsigned)gridDim.x * (unsigned)gen;
        unsigned v;
        do {
            asm volatile("ld.acquire.gpu.u32 %0, [%1];" : "=r"(v) : "l"(&g_barrier) : "memory");
            if (v >= target) break;
            __nanosleep(32);
        } while (true);
    }
    __syncthreads();
    gen++;
}

__device__ __forceinline__ float d4(float4 a, float4 b)
{ return a.x*b.x + a.y*b.y + a.z*b.z + a.w*b.w; }

__device__ __forceinline__ uint64_t mkpolicy()
{
    uint64_t p;
    asm volatile("createpolicy.fractional.L2::evict_last.b64 %0, 1.0;" : "=l"(p));
    return p;
}

__device__ __forceinline__ float4 ldg_el(const float4* p, uint64_t pol)
{
    float4 v;
    asm volatile("ld.global.L2::cache_hint.v4.f32 {%0,%1,%2,%3}, [%4], %5;"
        : "=f"(v.x), "=f"(v.y), "=f"(v.z), "=f"(v.w) : "l"(p), "l"(pol));
    return v;
}

__device__ __forceinline__ void cp16(uint32_t saddr, const void* g, bool pred)
{
    asm volatile("cp.async.ca.shared.global [%0], [%1], 16, %2;"
        :: "r"(saddr), "l"(g), "r"(pred ? 16 : 0));
}

typedef wmma::fragment<wmma::matrix_a, 16,16,8, wmma::precision::tf32, wmma::row_major> FragA;
typedef wmma::fragment<wmma::matrix_b, 16,16,8, wmma::precision::tf32, wmma::row_major> FragBR;
typedef wmma::fragment<wmma::matrix_b, 16,16,8, wmma::precision::tf32, wmma::col_major> FragBC;
typedef wmma::fragment<wmma::accumulator, 16,16,8, float> FragC;

template<class F>
__device__ __forceinline__ void split_frag(F& hi, F& lo)
{
#pragma unroll
    for (int i = 0; i < hi.num_elements; i++) {
        float r = hi.x[i];
        float h = wmma::__float_to_tf32(r);
        hi.x[i] = h;
        lo.x[i] = wmma::__float_to_tf32(r - h);
    }
}

template<bool BTR>
__device__ __forceinline__ void mma_tile(float* As, float* Bs, int mrow, int nq,
                                         FragC& c0, FragC& c1)
{
#pragma unroll
    for (int kk = 0; kk < 32; kk += 8) {
        FragA ah, al;
        wmma::load_matrix_sync(ah, As + mrow*16*40 + kk, 40);
        split_frag(ah, al);
        if (!BTR) {
            FragBR b0h,b0l,b1h,b1l;
            wmma::load_matrix_sync(b0h, Bs + kk*136 + nq*32, 136);
            wmma::load_matrix_sync(b1h, Bs + kk*136 + nq*32 + 16, 136);
            split_frag(b0h, b0l); split_frag(b1h, b1l);
            wmma::mma_sync(c0, ah, b0h, c0);
            wmma::mma_sync(c0, ah, b0l, c0);
            wmma::mma_sync(c0, al, b0h, c0);
            wmma::mma_sync(c1, ah, b1h, c1);
            wmma::mma_sync(c1, ah, b1l, c1);
            wmma::mma_sync(c1, al, b1h, c1);
        } else {
            FragBC b0h,b0l,b1h,b1l;
            wmma::load_matrix_sync(b0h, Bs + (nq*32)*40 + kk, 40);
            wmma::load_matrix_sync(b1h, Bs + (nq*32+16)*40 + kk, 40);
            split_frag(b0h, b0l); split_frag(b1h, b1l);
            wmma::mma_sync(c0, ah, b0h, c0);
            wmma::mma_sync(c0, ah, b0l, c0);
            wmma::mma_sync(c0, al, b0h, c0);
            wmma::mma_sync(c1, ah, b1h, c1);
            wmma::mma_sync(c1, ah, b1l, c1);
            wmma::mma_sync(c1, al, b1h, c1);
        }
    }
}

template<bool BTR>
__device__ __forceinline__ void gemm_pipe(
    const float* __restrict__ A, int M, int K, int lda,
    const float* __restrict__ B1, const float* __restrict__ B2,
    int N1, int N, int ldb1, int ldb2,
    float* __restrict__ part, size_t slab, int ldp,
    int m0, int n0, int kt0, int kt1, float* __restrict__ smbase)
{
    const int t = threadIdx.x;
    const int warp = t >> 5, mrow = warp >> 2, nq = warp & 3;
    FragC c0, c1;
    wmma::fill_fragment(c0, 0.f);
    wmma::fill_fragment(c1, 0.f);

    auto issue = [&](int kt, int bufi) {
        float* As = smbase + bufi*BUFF;
        float* Bs = As + 1280;
        int k0 = kt*32;
        {
            int mm = t >> 3, kq = t & 7;
            int mg = m0 + mm, kg = k0 + kq*4;
            bool ok = (mg < M) && (kg < K);
            uint32_t sa = (uint32_t)__cvta_generic_to_shared(&As[mm*40 + kq*4]);
            cp16(sa, &A[(size_t)mg*lda + kg], ok);
        }
        if (!BTR) {
            int kk = t >> 3, cc = t & 7;
            int kg = k0 + kk;
#pragma unroll
            for (int j = 0; j < 4; j++) {
                int nn = (cc + 8*j)*4;
                int ng = n0 + nn;
                bool ok = (kg < K) && (ng < N);
                const float* g = (ng < N1) ? &B1[(size_t)kg*ldb1 + ng]
                                           : &B2[(size_t)kg*ldb2 + (ng - N1)];
                uint32_t sa = (uint32_t)__cvta_generic_to_shared(&Bs[kk*136 + nn]);
                cp16(sa, g, ok);
            }
        } else {
            int n = t >> 1, half = t & 1;
            int ng = n0 + n;
            bool okrow = ng < N;
            const float* brow = okrow ? ((ng < N1) ? &B1[(size_t)ng*ldb1]
                                                   : &B2[(size_t)(ng-N1)*ldb2]) : B1;
#pragma unroll
            for (int j = 0; j < 4; j++) {
                int kg = k0 + half*16 + j*4;
                bool ok = okrow && (kg < K);
                uint32_t sa = (uint32_t)__cvta_generic_to_shared(&Bs[n*40 + half*16 + j*4]);
                cp16(sa, &brow[kg], ok);
            }
        }
        asm volatile("cp.async.commit_group;");
    };

    issue(kt0, 0);
    for (int kt = kt0; kt < kt1; kt++) {
        int bufi = (kt - kt0) & 1;
        bool more = (kt + 1 < kt1);
        if (more) issue(kt + 1, bufi ^ 1);
        if (more) asm volatile("cp.async.wait_group 1;");
        else      asm volatile("cp.async.wait_group 0;");
        __syncthreads();
        float* As = smbase + bufi*BUFF;
        mma_tile<BTR>(As, As + 1280, mrow, nq, c0, c1);
        __syncthreads();
    }
    float* cb = part + slab + (size_t)(m0 + mrow*16)*ldp + n0 + nq*32;
    wmma::store_matrix_sync(cb,      c0, ldp, wmma::mem_row_major);
    wmma::store_matrix_sync(cb + 16, c1, ldp, wmma::mem_row_major);
}

template<bool REDA, bool GATEA>
__device__ __forceinline__ void gemm_w(
    const float* __restrict__ A, int M, int K, int lda,
    int Zred, size_t slabA, float ascale, const float* __restrict__ gateA,
    const float* __restrict__ B1, const float* __restrict__ B2,
    int N1, int N, int ldb1, int ldb2,
    float* __restrict__ part, size_t slab, int ldp,
    int m0, int n0, int kt0, int kt1, float* __restrict__ smbase)
{
    const int t = threadIdx.x;
    const int warp = t >> 5, mrow = warp >> 2, nq = warp & 3;
    float* As = smbase;
    float* Bs = smbase + 1280;
    FragC c0, c1;
    wmma::fill_fragment(c0, 0.f);
    wmma::fill_fragment(c1, 0.f);

    for (int kt = kt0; kt < kt1; kt++) {
        int k0 = kt*32;
        {
            int mm = t >> 3, kq = (t & 7)*4;
            int mg = m0 + mm, kg = k0 + kq;
            float4 v = make_float4(0,0,0,0);
            if (mg < M && kg + 3 < K) {
                if (REDA) {
                    for (int z = 0; z < Zred; z++) {
                        float4 w = *(const float4*)&A[(size_t)z*slabA + (size_t)mg*lda + kg];
                        v.x+=w.x; v.y+=w.y; v.z+=w.z; v.w+=w.w;
                    }
                } else v = *(const float4*)&A[(size_t)mg*lda + kg];
                v.x*=ascale; v.y*=ascale; v.z*=ascale; v.w*=ascale;
                if (GATEA) {
                    float4 g = *(const float4*)&gateA[(size_t)mg*lda + kg];
                    v.x*=g.x; v.y*=g.y; v.z*=g.z; v.w*=g.w;
                }
            } else if (mg < M) {
                float tmp[4] = {0,0,0,0};
                for (int j = 0; j < 4; j++) {
                    int k2 = kg + j;
                    if (k2 < K) {
                        float s = 0.f;
                        if (REDA) { for (int z=0; z<Zred; z++) s += A[(size_t)z*slabA + (size_t)mg*lda + k2]; }
                        else s = A[(size_t)mg*lda + k2];
                        s *= ascale;
                        if (GATEA) s *= gateA[(size_t)mg*lda + k2];
                        tmp[j] = s;
                    }
                }
                v = make_float4(tmp[0],tmp[1],tmp[2],tmp[3]);
            }
            *(float4*)&As[ (t>>3)*40 + (t&7)*4 ] = v;
        }
        {
            int kk = t >> 3, cc = t & 7;
            int kg = k0 + kk;
#pragma unroll
            for (int j = 0; j < 4; j++) {
                int nn = (cc + 8*j)*4;
                int ng = n0 + nn;
                float4 v = make_float4(0,0,0,0);
                if (kg < K && ng < N) {
                    if (ng < N1) v = *(const float4*)&B1[(size_t)kg*ldb1 + ng];
                    else         v = *(const float4*)&B2[(size_t)kg*ldb2 + (ng-N1)];
                }
                *(float4*)&Bs[kk*136 + nn] = v;
            }
        }
        __syncthreads();
        mma_tile<false>(As, Bs, mrow, nq, c0, c1);
        __syncthreads();
    }
    float* cb = part + slab + (size_t)(m0 + mrow*16)*ldp + n0 + nq*32;
    wmma::store_matrix_sync(cb,      c0, ldp, wmma::mem_row_major);
    wmma::store_matrix_sync(cb + 16, c1, ldp, wmma::mem_row_major);
}

// stage unit counts (tail stages widened for 3-blocks/SM grid)
#define U_MLP   40
#define U_QP1   320
#define S0U     (U_MLP+U_QP1)     // 360
#define U_QP2   200
#define U_AVG   256
#define S1U     (U_QP2+U_AVG)     // 456
#define U_QR    160
#define U_GATP  154
#define S2U     (U_QR+U_GATP)     // 314
#define U_GR    166
#define U_QK    440
#define S3U     (U_GR+U_QK)       // 606

__global__ void __launch_bounds__(256, 3) fused_k(
    const float* __restrict__ sc,  const float* __restrict__ bw,
    const float* __restrict__ ss,  const float* __restrict__ bsm,
    const float* __restrict__ qf,
    const float* __restrict__ Wm1, const float* __restrict__ bm1,
    const float* __restrict__ Wm2, const float* __restrict__ bm2,
    const float* __restrict__ Wvis,const float* __restrict__ bvis,
    const float* __restrict__ Wsem,const float* __restrict__ bsem,
    const float* __restrict__ Wq,  const float* __restrict__ Wk,
    const float* __restrict__ Wv,  const float* __restrict__ Wqs,
    const float* __restrict__ Wks, const float* __restrict__ Wfc,
    const float* __restrict__ temp, float* __restrict__ outL)
{
    extern __shared__ __align__(32) float sm[];
    const int NBLK = gridDim.x;
    const int t = threadIdx.x;
    const uint64_t pol = mkpolicy();
    int gen = 1;

    // ===== S0: MLP | qp1 (sc@Wq, pipelined) =====
    for (int u = blockIdx.x; u < S0U; u += NBLK) {
        if (u < U_MLP) {
            int m0u = u * 4;
            for (int i = t; i < 4*SEM; i += 256)
                sm[i] = ss[(size_t)(m0u + i/SEM)*SEM + (i % SEM)];
            __syncthreads();
            for (int n = t; n < SEM; n += 256) {
                float a0 = bm1[n], a1 = a0, a2 = a0, a3 = a0;
                for (int k = 0; k < SEM; k++) {
                    float w = Wm1[(size_t)k*SEM + n];
                    a0 = fmaf(sm[0*SEM+k], w, a0); a1 = fmaf(sm[1*SEM+k], w, a1);
                    a2 = fmaf(sm[2*SEM+k], w, a2); a3 = fmaf(sm[3*SEM+k], w, a3);
                }
                sm[1280 + 0*SEM + n] = (a0 >= 0.f) ? a0 : 0.1f*a0;
                sm[1280 + 1*SEM + n] = (a1 >= 0.f) ? a1 : 0.1f*a1;
                sm[1280 + 2*SEM + n] = (a2 >= 0.f) ? a2 : 0.1f*a2;
                sm[1280 + 3*SEM + n] = (a3 >= 0.f) ? a3 : 0.1f*a3;
            }
            __syncthreads();
            for (int n = t; n < SEM; n += 256) {
                float a0 = bm2[n], a1 = a0, a2 = a0, a3 = a0;
                for (int k = 0; k < SEM; k++) {
                    float w = Wm2[(size_t)k*SEM + n];
                    a0 = fmaf(sm[1280+0*SEM+k], w, a0); a1 = fmaf(sm[1280+1*SEM+k], w, a1);
                    a2 = fmaf(sm[1280+2*SEM+k], w, a2); a3 = fmaf(sm[1280+3*SEM+k], w, a3);
                }
                g_scal[(size_t)(m0u+0)*SEM + n] = a0;
                g_scal[(size_t)(m0u+1)*SEM + n] = a1;
                g_scal[(size_t)(m0u+2)*SEM + n] = a2;
                g_scal[(size_t)(m0u+3)*SEM + n] = a3;
            }
            __syncthreads();
        } else {
            int uu = u - U_MLP;
            int z = uu & 7, r = uu >> 3;
            int nt = r & 7, mt = r >> 3;
            gemm_pipe<false>(sc, BTOT, FD, FD, Wq, Wq, FD, FD, FD, FD,
                g_part, (size_t)z*MNq, FD, mt*32, nt*128, z*4, z*4+4, sm);
        }
    }
    gsync(gen);

    // ===== S1: qp2 (s@Wqs, pipelined) | avg partials (evict_last) =====
    for (int u = blockIdx.x; u < S1U; u += NBLK) {
        if (u < U_QP2) {
            int z = u % 5, r = u / 5;
            int nt = r & 7, mt = r >> 3;
            gemm_pipe<false>(g_scal, BTOT, SEM, SEM, Wqs, Wqs, FD, FD, FD, FD,
                g_part, (size_t)(8+z)*MNq, FD, mt*32, nt*128, z*2, z*2+2, sm);
        } else {
            int uu = u - U_QP2;
            int chunk = uu >> 6, r = uu & 63;
            int b = r >> 1, cpart = r & 1;
            int c4 = cpart*256 + t;
            if (c4 < CATD/4) {
                int c = c4*4;
                int n0 = chunk*128;
                float4 v = make_float4(0,0,0,0);
                if (c < FD) {
                    const float4* p = (const float4*)bw + ((size_t)b*NB + n0)*(FD/4) + c4;
#pragma unroll 16
                    for (int n = 0; n < 128; n++) {
                        float4 x = ldg_el(&p[(size_t)n*(FD/4)], pol);
                        v.x+=x.x; v.y+=x.y; v.z+=x.z; v.w+=x.w;
                    }
                } else {
                    const float4* p = (const float4*)(bsm + ((size_t)b*NB + n0)*SEM + (c-FD));
#pragma unroll 16
                    for (int n = 0; n < 128; n++) {
                        float4 x = ldg_el(&p[(size_t)n*(SEM/4)], pol);
                        v.x+=x.x; v.y+=x.y; v.z+=x.z; v.w+=x.w;
                    }
                }
                *(float4*)&g_avgp[(size_t)chunk*BS*CATD + (size_t)b*CATD + c] = v;
            }
        }
    }
    gsync(gen);

    // ===== S2: q reduce | gates GEMM partials =====
    for (int u = blockIdx.x; u < S2U; u += NBLK) {
        if (u < U_QR) {
            size_t i4 = (size_t)u*256 + t;
            float4 v = make_float4(0,0,0,0);
#pragma unroll
            for (int z = 0; z < 13; z++) {
                float4 w = ((const float4*)g_part)[(size_t)z*(MNq/4) + i4];
                v.x+=w.x; v.y+=w.y; v.z+=w.z; v.w+=w.w;
            }
            ((float4*)g_q)[i4] = v;
        } else {
            int uu = u - U_QR;
            int z = uu % 14, nt = uu / 14;
            gemm_w<true,false>(g_avgp, BS, CATD, CATD, 4, (size_t)BS*CATD, 1.f/NB, nullptr,
                Wvis, Wsem, FD, CATD, FD, SEM,
                g_part2, (size_t)z*SLABG, 1408, 0, nt*128, z*3, z*3+3, sm);
        }
    }
    gsync(gen);

    // ===== S3: gates reduce | qk GEMM =====
    for (int u = blockIdx.x; u < S3U; u += NBLK) {
        if (u < U_GR) {
            size_t i = (size_t)u*256 + t;
            if (i < (size_t)BS*CATD) {
                int m = (int)(i / CATD), n = (int)(i % CATD);
                float v = 0.f;
#pragma unroll
                for (int z = 0; z < 14; z++) v += g_part2[(size_t)z*SLABG + (size_t)m*1408 + n];
                if (n < FD) {
                    v += bvis[n];
                    g_gv[(size_t)m*FD + n] = 1.f + 1.f/(1.f + __expf(-v));
                } else {
                    v += bsem[n - FD];
                    g_gs[(size_t)m*SEM + (n - FD)] = 1.f + 1.f/(1.f + __expf(-v));
                }
            }
        } else {
            int uu = u - U_GR;
            int z = uu & 7, r = uu >> 3;
            int nt = r % 11, mt = r / 11;
            gemm_pipe<true>(g_q, BTOT, FD, FD, Wk, Wks, FD, CATD, FD, FD,
                g_part, (size_t)z*SLABK, 1408, mt*32, nt*128, z*4, z*4+4, sm);
        }
    }
    gsync(gen);

    // ===== S4: qk reduce * gates =====
    for (int u = blockIdx.x; u < 828; u += NBLK) {
        size_t i = (size_t)u*256 + t;
        if (i < (size_t)MNk) {
            int m = (int)(i / CATD), n = (int)(i % CATD);
            float v = 0.f;
#pragma unroll
            for (int z = 0; z < 8; z++) v += g_part[(size_t)z*SLABK + (size_t)m*1408 + n];
            int b = m / NWAY;
            if (n < FD) g_qkg [(size_t)m*FD  + n]      = v * g_gv[(size_t)b*FD  + n];
            else        g_qksg[(size_t)m*SEM + (n-FD)] = v * g_gs[(size_t)b*SEM + (n-FD)];
        }
    }
    gsync(gen);

    // ===== S5: scores (4 rows per warp, 512 units) =====
    for (int u = blockIdx.x; u < 512; u += NBLK) {
        int b = u / 16, ch = u % 16;
        int w = t >> 5, lane = t & 31;
        int nbase = ch*32 + w*4;
        float acc[4][5];
#pragma unroll
        for (int j = 0; j < 4; j++)
#pragma unroll
            for (int p = 0; p < 5; p++) acc[j][p] = 0.f;
        const float4* qkg4 = (const float4*)g_qkg  + (size_t)b*NWAY*(FD/4);
        const float4* qks4 = (const float4*)g_qksg + (size_t)b*NWAY*(SEM/4);
        const float4* bw4  = (const float4*)bw     + (size_t)b*NB*(FD/4);
        const float4* bs4  = (const float4*)bsm    + (size_t)b*NB*(SEM/4);
#pragma unroll
        for (int tt = 0; tt < 8; tt++) {
            int c = tt*32 + lane;
            float4 qv[5];
#pragma unroll
            for (int p = 0; p < 5; p++) qv[p] = qkg4[p*(FD/4) + c];
#pragma unroll
            for (int j = 0; j < 4; j++) {
                float4 x = ldg_el(&bw4[(size_t)(nbase+j)*(FD/4) + c], pol);
#pragma unroll
                for (int p = 0; p < 5; p++) acc[j][p] += d4(x, qv[p]);
            }
        }
#pragma unroll
        for (int tt = 0; tt < 3; tt++) {
            int c = tt*32 + lane;
            bool ok = c < (SEM/4);
            float4 qv[5];
#pragma unroll
            for (int p = 0; p < 5; p++)
                qv[p] = ok ? qks4[p*(SEM/4) + c] : make_float4(0,0,0,0);
#pragma unroll
            for (int j = 0; j < 4; j++) {
                float4 x = ok ? ldg_el(&bs4[(size_t)(nbase+j)*(SEM/4) + c], pol) : make_float4(0,0,0,0);
#pragma unroll
                for (int p = 0; p < 5; p++) acc[j][p] += d4(x, qv[p]);
            }
        }
#pragma unroll
        for (int off = 16; off; off >>= 1)
#pragma unroll
            for (int j = 0; j < 4; j++)
#pragma unroll
                for (int p = 0; p < 5; p++)
                    acc[j][p] += __shfl_xor_sync(0xffffffffu, acc[j][p], off);
#pragma unroll
        for (int j = 0; j < 4; j++)
            if (lane == j) {
                int n = nbase + j;
#pragma unroll
                for (int p = 0; p < 5; p++)
                    g_scr[(size_t)(b*NWAY+p)*NB + n] = acc[j][p] * (1.f/32.f);
            }
    }
    gsync(gen);

    // ===== S6: fused softmax + nway-avg attention + mix partials (512 units, 32-row chunks) =====
    for (int u = blockIdx.x; u < 512; u += NBLK) {
        int b = u >> 4, chunk = u & 15;
        int n0 = chunk*32;
        int w = t >> 5, lane = t & 31;
        for (int i = t; i < NWAY*NB; i += 256)
            sm[i] = g_scr[(size_t)b*NWAY*NB + i];
        __syncthreads();
        float mx[5];
#pragma unroll
        for (int p = 0; p < 5; p++)
            mx[p] = fmaxf(sm[p*NB + t], sm[p*NB + 256 + t]);
#pragma unroll
        for (int off = 16; off; off >>= 1)
#pragma unroll
            for (int p = 0; p < 5; p++)
                mx[p] = fmaxf(mx[p], __shfl_xor_sync(0xffffffffu, mx[p], off));
        if (lane == 0)
#pragma unroll
            for (int p = 0; p < 5; p++) sm[2624 + w*5 + p] = mx[p];
        __syncthreads();
        if (t < 5) {
            float m = sm[2624 + t];
            for (int w2 = 1; w2 < 8; w2++) m = fmaxf(m, sm[2624 + w2*5 + t]);
            sm[2680 + t] = m;
        }
        __syncthreads();
        float sme[5];
#pragma unroll
        for (int p = 0; p < 5; p++) {
            float m = sm[2680 + p];
            sme[p] = __expf(sm[p*NB + t] - m) + __expf(sm[p*NB + 256 + t] - m);
        }
#pragma unroll
        for (int off = 16; off; off >>= 1)
#pragma unroll
            for (int p = 0; p < 5; p++)
                sme[p] += __shfl_xor_sync(0xffffffffu, sme[p], off);
        if (lane == 0)
#pragma unroll
            for (int p = 0; p < 5; p++) sm[2624 + w*5 + p] = sme[p];
        __syncthreads();
        if (t < 5) {
            float s = 0.f;
            for (int w2 = 0; w2 < 8; w2++) s += sm[2624 + w2*5 + t];
            sm[2688 + t] = 1.f / s;
        }
        __syncthreads();
        if (t < 32) {
            int n = n0 + t;
            float a = 0.f;
#pragma unroll
            for (int p = 0; p < 5; p++)
                a += __expf(sm[p*NB + n] - sm[2680 + p]) * sm[2688 + p];
            sm[2696 + t] = a * (1.f/NWAY);
        }
        __syncthreads();
        float4 acc = make_float4(0,0,0,0);
        const float4* p4 = (const float4*)bw + ((size_t)b*NB + n0)*(FD/4) + t;
#pragma unroll 16
        for (int r = 0; r < 32; r++) {
            float4 x = p4[(size_t)r*(FD/4)];
            float a = sm[2696 + r];
            acc.x = fmaf(x.x, a, acc.x); acc.y = fmaf(x.y, a, acc.y);
            acc.z = fmaf(x.z, a, acc.z); acc.w = fmaf(x.w, a, acc.w);
        }
        ((float4*)g_mixp)[(size_t)chunk*(SLABF/4) + (size_t)b*(FD/4) + t] = acc;
        __syncthreads();
    }
    gsync(gen);

    // ===== S7: fakev = (mixavg * gv) @ Wv, split-K 32 (256 units) =====
    for (int u = blockIdx.x; u < 256; u += NBLK) {
        int z = u & 31, nt = u >> 5;
        gemm_w<true,true>(g_mixp, BS, FD, FD, 16, (size_t)SLABF, 1.f, g_gv,
            Wv, Wv, FD, FD, FD, FD,
            g_part, (size_t)z*SLABF, FD, 0, nt*128, z, z+1, sm);
    }
    gsync(gen);

    // ===== S8: fakefc = reduce(fakev) @ Wfc, split-K 32 (256 units, slabs 32..63) =====
    for (int u = blockIdx.x; u < 256; u += NBLK) {
        int z = u & 31, nt = u >> 5;
        gemm_w<true,false>(g_part, BS, FD, FD, 32, (size_t)SLABF, 1.f, nullptr,
            Wfc, Wfc, FD, FD, FD, FD,
            g_part, (size_t)(32+z)*SLABF, FD, 0, nt*128, z, z+1, sm);
    }
    gsync(gen);

    // ===== S9: fake + norms + logits =====
    for (int u = blockIdx.x; u < BS*10; u += NBLK) {
        int b = u / 10, qc = u % 10;
        {
            const float4* sc4 = (const float4*)sc + (size_t)b*NWAY*(FD/4);
            float4 f = make_float4(0,0,0,0);
            float sq[6];
#pragma unroll
            for (int c = 0; c < NWAY; c++) {
                float4 o = sc4[c*(FD/4) + t];
                sq[c] = d4(o, o);
                f.x+=o.x; f.y+=o.y; f.z+=o.z; f.w+=o.w;
            }
            f.x*=0.2f; f.y*=0.2f; f.z*=0.2f; f.w*=0.2f;
#pragma unroll
            for (int z = 32; z < 64; z++) {
                float4 w2 = ((const float4*)g_part)[(size_t)z*(SLABF/4) + (size_t)b*(FD/4) + t];
                f.x+=w2.x; f.y+=w2.y; f.z+=w2.z; f.w+=w2.w;
            }
            ((float4*)sm)[t] = f;
            sq[5] = d4(f, f);
#pragma unroll
            for (int off = 16; off; off >>= 1)
#pragma unroll
                for (int r = 0; r < 6; r++)
                    sq[r] += __shfl_xor_sync(0xffffffffu, sq[r], off);
            int lane = t & 31, w = t >> 5;
            if (lane == 0)
#pragma unroll
                for (int r = 0; r < 6; r++) sm[1024 + w*6 + r] = sq[r];
            __syncthreads();
            if (t < 6) {
                float s = 0.f;
                for (int w2 = 0; w2 < 8; w2++) s += sm[1024 + w2*6 + t];
                sm[1072 + t] = 1.f / sqrtf(s);
            }
            __syncthreads();
        }
        {
            int w = t >> 5, lane = t & 31;
            int iq = qc*8 + w;
            if (iq < NQ) {
                const float4* q4  = (const float4*)qf + ((size_t)b*NQ + iq)*(FD/4);
                const float4* sc4 = (const float4*)sc + (size_t)b*NWAY*(FD/4);
                const float4* f4  = (const float4*)sm;
                float qq = 0.f, d[6] = {0,0,0,0,0,0};
                for (int i = lane; i < FD/4; i += 32) {
                    float4 x = q4[i];
                    qq += d4(x, x);
#pragma unroll
                    for (int r = 0; r < NWAY; r++) d[r] += d4(x, sc4[r*(FD/4) + i]);
                    d[5] += d4(x, f4[i]);
                }
#pragma unroll
                for (int off = 16; off; off >>= 1) {
                    qq += __shfl_xor_sync(0xffffffffu, qq, off);
#pragma unroll
                    for (int r = 0; r < 6; r++) d[r] += __shfl_xor_sync(0xffffffffu, d[r], off);
                }
                if (lane == 0) {
                    float s = temp[0] / sqrtf(qq);
                    float* o = outL + ((size_t)b*NQ + iq)*6;
#pragma unroll
                    for (int r = 0; r < 6; r++) o[r] = d[r] * s * sm[1072 + r];
                }
            }
        }
        __syncthreads();
    }
}

// ---------------- host ----------------
extern "C" void kernel_launch(void* const* d_in, const int* in_sizes, int n_in,
                              void* d_out, int out_size)
{
    const float* sc   = (const float*)d_in[0];
    const float* bw   = (const float*)d_in[1];
    const float* ss   = (const float*)d_in[2];
    const float* bsm  = (const float*)d_in[3];
    const float* qf   = (const float*)d_in[4];
    const float* Wm1  = (const float*)d_in[5];
    const float* bm1  = (const float*)d_in[6];
    const float* Wm2  = (const float*)d_in[7];
    const float* bm2  = (const float*)d_in[8];
    const float* Wvis = (const float*)d_in[9];
    const float* bvis = (const float*)d_in[10];
    const float* Wsem = (const float*)d_in[11];
    const float* bsem = (const float*)d_in[12];
    const float* Wq   = (const float*)d_in[13];
    const float* Wk   = (const float*)d_in[14];
    const float* Wv   = (const float*)d_in[15];
    const float* Wqs  = (const float*)d_in[16];
    const float* Wks  = (const float*)d_in[17];
    const float* Wfc  = (const float*)d_in[18];
    const float* temp = (const float*)d_in[19];
    float* out = (float*)d_out;

    const int smem_bytes = SMEMF * sizeof(float);  // 51200
    cudaFuncSetAttribute(fused_k, cudaFuncAttributeMaxDynamicSharedMemorySize, smem_bytes);

    int dev = 0;
    cudaGetDevice(&dev);
    int nsm = 148;
    cudaDeviceGetAttribute(&nsm, cudaDevAttrMultiProcessorCount, dev);
    int bpm = 1;
    cudaOccupancyMaxActiveBlocksPerMultiprocessor(&bpm, fused_k, 256, smem_bytes);
    if (bpm < 1) bpm = 1;
    int nblk = nsm * bpm;

    void* barp = nullptr;
    cudaGetSymbolAddress(&barp, g_barrier);
    cudaMemsetAsync(barp, 0, sizeof(unsigned int), 0);

    fused_k<<<nblk, 256, smem_bytes>>>(sc, bw, ss, bsm, qf, Wm1, bm1, Wm2, bm2,
                                       Wvis, bvis, Wsem, bsem, Wq, Wk, Wv, Wqs, Wks, Wfc,
                                       temp, out);
}